// round 7
// baseline (speedup 1.0000x reference)
#include <cuda_runtime.h>

// Problem constants
#define DD 160
#define HH 192
#define WW 160
#define DHW (DD*HH*WW)          // 4,915,200 (divisible by 4 -> channel planes stay 16B aligned)
#define BB 2
#define CC 2

__device__ __forceinline__ float pick4(const float4& v, int sel) {
    // dynamic element select from float4 without local memory
    float lo = (sel & 2) ? v.z : v.x;
    float hi = (sel & 2) ? v.w : v.y;
    return (sel & 1) ? hi : lo;
}

__global__ __launch_bounds__(256)
void warp3d_kernel(const float* __restrict__ x,
                   const float* __restrict__ flow,
                   float* __restrict__ out)
{
    int idx = blockIdx.x * blockDim.x + threadIdx.x;
    if (idx >= BB * DHW) return;

    int b = idx / DHW;
    int s = idx - b * DHW;
    int xw = s % WW;
    int t  = s / WW;
    int yh = t % HH;
    int zd = t / HH;

    const float* fb = flow + (size_t)b * 3 * DHW;
    float pz = (float)zd + fb[s];
    float py = (float)yh + fb[s + DHW];
    float px = (float)xw + fb[s + 2 * DHW];

    float z0f = floorf(pz), y0f = floorf(py), x0f = floorf(px);
    float fz = pz - z0f, fy = py - y0f, fx = px - x0f;
    int z0 = (int)z0f, y0 = (int)y0f, x0 = (int)x0f;
    int z1 = z0 + 1, y1 = y0 + 1, x1 = x0 + 1;

    // per-axis weights, zeroed when the corner index is out of bounds
    float wz0 = (z0 >= 0 && z0 < DD) ? (1.0f - fz) : 0.0f;
    float wz1 = (z1 >= 0 && z1 < DD) ? fz          : 0.0f;
    float wy0 = (y0 >= 0 && y0 < HH) ? (1.0f - fy) : 0.0f;
    float wy1 = (y1 >= 0 && y1 < HH) ? fy          : 0.0f;
    float wx0 = (x0 >= 0 && x0 < WW) ? (1.0f - fx) : 0.0f;
    float wx1 = (x1 >= 0 && x1 < WW) ? fx          : 0.0f;

    // clamped indices
    int zc0 = min(max(z0, 0), DD - 1);
    int zc1 = min(max(z1, 0), DD - 1);
    int yc0 = min(max(y0, 0), HH - 1);
    int yc1 = min(max(y1, 0), HH - 1);
    int xc0 = min(max(x0, 0), WW - 1);
    int xc1 = min(max(x1, 0), WW - 1);

    // x-pair vector-load plan (shared by all 4 row-groups: row bases are
    // multiples of WW=160, i.e. 16B-aligned, so sel depends only on xc0)
    int axc0 = xc0 & ~3;          // aligned float4 start within the row
    int sel  = xc0 & 3;           // position of xc0 inside the float4
    int dxc  = xc1 - xc0;         // 0 (clamped equal) or 1
    bool extra = (sel == 3) && (dxc == 1);   // xc1 falls outside the float4
    int sel1 = extra ? 3 : (sel + dxc);      // select for xc1 when no extra load

    // row-group weights (z,y combined)
    float wzy00 = wz0 * wy0;
    float wzy01 = wz0 * wy1;
    float wzy10 = wz1 * wy0;
    float wzy11 = wz1 * wy1;

    int base00 = (zc0 * HH + yc0) * WW + axc0;
    int base01 = (zc0 * HH + yc1) * WW + axc0;
    int base10 = (zc1 * HH + yc0) * WW + axc0;
    int base11 = (zc1 * HH + yc1) * WW + axc0;

    const float* xb0 = x + (size_t)b * CC * DHW;   // channel 0
    const float* xb1 = xb0 + DHW;                  // channel 1

    float a0 = 0.0f, a1 = 0.0f;

    #define ROWGROUP(BASE, WZY)                                              \
    {                                                                        \
        float4 v0 = __ldg((const float4*)(xb0 + (BASE)));                    \
        float4 v1 = __ldg((const float4*)(xb1 + (BASE)));                    \
        float e00 = pick4(v0, sel);                                          \
        float e10 = pick4(v1, sel);                                          \
        float e01, e11;                                                      \
        if (extra) {                                                         \
            e01 = __ldg(xb0 + (BASE) + 4);                                   \
            e11 = __ldg(xb1 + (BASE) + 4);                                   \
        } else {                                                             \
            e01 = pick4(v0, sel1);                                           \
            e11 = pick4(v1, sel1);                                           \
        }                                                                    \
        a0 = fmaf((WZY), fmaf(e00, wx0, e01 * wx1), a0);                     \
        a1 = fmaf((WZY), fmaf(e10, wx0, e11 * wx1), a1);                     \
    }

    ROWGROUP(base00, wzy00)
    ROWGROUP(base01, wzy01)
    ROWGROUP(base10, wzy10)
    ROWGROUP(base11, wzy11)

    #undef ROWGROUP

    float* ob = out + (size_t)b * CC * DHW;
    ob[s]       = a0;
    ob[s + DHW] = a1;
}

extern "C" void kernel_launch(void* const* d_in, const int* in_sizes, int n_in,
                              void* d_out, int out_size)
{
    const float* x    = (const float*)d_in[0];
    const float* flow = (const float*)d_in[1];
    float* out        = (float*)d_out;

    const int N = BB * DHW;
    const int threads = 256;
    const int blocks = (N + threads - 1) / threads;
    warp3d_kernel<<<blocks, threads>>>(x, flow, out);
}

// round 8
// speedup vs baseline: 1.0015x; 1.0015x over previous
#include <cuda_runtime.h>

// Problem constants
#define DD 160
#define HH 192
#define WW 160
#define DHW (DD*HH*WW)          // 4,915,200 (divisible by 4 -> channel planes stay 16B aligned)
#define BB 2
#define CC 2

__device__ __forceinline__ float pick4(const float4& v, int sel) {
    // dynamic element select from float4 without local memory
    float lo = (sel & 2) ? v.z : v.x;
    float hi = (sel & 2) ? v.w : v.y;
    return (sel & 1) ? hi : lo;
}

__global__ __launch_bounds__(256)
void warp3d_kernel(const float* __restrict__ x,
                   const float* __restrict__ flow,
                   float* __restrict__ out)
{
    int idx = blockIdx.x * blockDim.x + threadIdx.x;
    if (idx >= BB * DHW) return;

    int b = idx / DHW;
    int s = idx - b * DHW;
    int xw = s % WW;
    int t  = s / WW;
    int yh = t % HH;
    int zd = t / HH;

    const float* fb = flow + (size_t)b * 3 * DHW;
    float pz = (float)zd + fb[s];
    float py = (float)yh + fb[s + DHW];
    float px = (float)xw + fb[s + 2 * DHW];

    float z0f = floorf(pz), y0f = floorf(py), x0f = floorf(px);
    float fz = pz - z0f, fy = py - y0f, fx = px - x0f;
    int z0 = (int)z0f, y0 = (int)y0f, x0 = (int)x0f;
    int z1 = z0 + 1, y1 = y0 + 1, x1 = x0 + 1;

    // per-axis weights, zeroed when the corner index is out of bounds
    float wz0 = (z0 >= 0 && z0 < DD) ? (1.0f - fz) : 0.0f;
    float wz1 = (z1 >= 0 && z1 < DD) ? fz          : 0.0f;
    float wy0 = (y0 >= 0 && y0 < HH) ? (1.0f - fy) : 0.0f;
    float wy1 = (y1 >= 0 && y1 < HH) ? fy          : 0.0f;
    float wx0 = (x0 >= 0 && x0 < WW) ? (1.0f - fx) : 0.0f;
    float wx1 = (x1 >= 0 && x1 < WW) ? fx          : 0.0f;

    // clamped indices
    int zc0 = min(max(z0, 0), DD - 1);
    int zc1 = min(max(z1, 0), DD - 1);
    int yc0 = min(max(y0, 0), HH - 1);
    int yc1 = min(max(y1, 0), HH - 1);
    int xc0 = min(max(x0, 0), WW - 1);
    int xc1 = min(max(x1, 0), WW - 1);

    // x-pair vector-load plan (shared by all 4 row-groups: row bases are
    // multiples of WW=160, i.e. 16B-aligned, so sel depends only on xc0)
    int axc0 = xc0 & ~3;          // aligned float4 start within the row
    int sel  = xc0 & 3;           // position of xc0 inside the float4
    int dxc  = xc1 - xc0;         // 0 (clamped equal) or 1
    bool extra = (sel == 3) && (dxc == 1);   // xc1 falls outside the float4
    int sel1 = extra ? 3 : (sel + dxc);      // select for xc1 when no extra load

    // row-group weights (z,y combined)
    float wzy00 = wz0 * wy0;
    float wzy01 = wz0 * wy1;
    float wzy10 = wz1 * wy0;
    float wzy11 = wz1 * wy1;

    int base00 = (zc0 * HH + yc0) * WW + axc0;
    int base01 = (zc0 * HH + yc1) * WW + axc0;
    int base10 = (zc1 * HH + yc0) * WW + axc0;
    int base11 = (zc1 * HH + yc1) * WW + axc0;

    const float* xb0 = x + (size_t)b * CC * DHW;   // channel 0
    const float* xb1 = xb0 + DHW;                  // channel 1

    float a0 = 0.0f, a1 = 0.0f;

    #define ROWGROUP(BASE, WZY)                                              \
    {                                                                        \
        float4 v0 = __ldg((const float4*)(xb0 + (BASE)));                    \
        float4 v1 = __ldg((const float4*)(xb1 + (BASE)));                    \
        float e00 = pick4(v0, sel);                                          \
        float e10 = pick4(v1, sel);                                          \
        float e01, e11;                                                      \
        if (extra) {                                                         \
            e01 = __ldg(xb0 + (BASE) + 4);                                   \
            e11 = __ldg(xb1 + (BASE) + 4);                                   \
        } else {                                                             \
            e01 = pick4(v0, sel1);                                           \
            e11 = pick4(v1, sel1);                                           \
        }                                                                    \
        a0 = fmaf((WZY), fmaf(e00, wx0, e01 * wx1), a0);                     \
        a1 = fmaf((WZY), fmaf(e10, wx0, e11 * wx1), a1);                     \
    }

    ROWGROUP(base00, wzy00)
    ROWGROUP(base01, wzy01)
    ROWGROUP(base10, wzy10)
    ROWGROUP(base11, wzy11)

    #undef ROWGROUP

    float* ob = out + (size_t)b * CC * DHW;
    ob[s]       = a0;
    ob[s + DHW] = a1;
}

extern "C" void kernel_launch(void* const* d_in, const int* in_sizes, int n_in,
                              void* d_out, int out_size)
{
    const float* x    = (const float*)d_in[0];
    const float* flow = (const float*)d_in[1];
    float* out        = (float*)d_out;

    const int N = BB * DHW;
    const int threads = 256;
    const int blocks = (N + threads - 1) / threads;
    warp3d_kernel<<<blocks, threads>>>(x, flow, out);
}